// round 14
// baseline (speedup 1.0000x reference)
#include <cuda_runtime.h>
#include <math.h>

typedef unsigned long long u64;
typedef unsigned int u32;

#define BN 4
#define HN 128
#define WN 128
#define CN 768
#define WFQ 65
#define ROWST (WFQ*CN)              /* 49920 u64 per (b,h) row */
#define NELEM (BN*HN*WFQ*CN)        /* 25,559,040 complex */

// Scratch complex buffers (re = low 32 bits, im = high 32 bits)
__device__ __align__(128) u64 g_A[NELEM];
__device__ __align__(128) u64 g_B[NELEM];
// Twiddle tables (128th roots of unity), cmul-ready pairs
__device__ __align__(16) u64 g_twF[256];   // pairs (c,c),(s,-s)   fwd  e^{-i}
__device__ __align__(16) u64 g_twI[256];   // pairs (c,c),(-s,s)   inv  e^{+i}

__device__ __forceinline__ u64 pk2(float lo, float hi){
    u64 r; asm("mov.b64 %0,{%1,%2};":"=l"(r):"f"(lo),"f"(hi)); return r;
}
__device__ __forceinline__ void upk2(u64 v, float& lo, float& hi){
    asm("mov.b64 {%0,%1},%2;":"=f"(lo),"=f"(hi):"l"(v));
}
__device__ __forceinline__ u64 fma2(u64 a, u64 b, u64 c){
    u64 d; asm("fma.rn.f32x2 %0,%1,%2,%3;":"=l"(d):"l"(a),"l"(b),"l"(c)); return d;
}
__device__ __forceinline__ u64 mul2(u64 a, u64 b){
    u64 d; asm("mul.rn.f32x2 %0,%1,%2;":"=l"(d):"l"(a),"l"(b)); return d;
}
__device__ __forceinline__ u64 add2(u64 a, u64 b){
    u64 d; asm("add.rn.f32x2 %0,%1,%2;":"=l"(d):"l"(a),"l"(b)); return d;
}
__device__ __forceinline__ u64 swp2(u64 v){
    float lo,hi; upk2(v,lo,hi); return pk2(hi,lo);
}
__device__ __forceinline__ float sshrink(float v){
    return copysignf(fmaxf(fabsf(v)-0.01f,0.0f), v);
}
__device__ __forceinline__ u32 smem_u32(const void* p){
    u32 a; asm("{ .reg .u64 t; cvta.to.shared.u64 t, %1; cvt.u32.u64 %0, t; }"
               : "=r"(a) : "l"(p)); return a;
}
__device__ __forceinline__ void cpa8(u32 saddr, const void* g){
    asm volatile("cp.async.ca.shared.global [%0], [%1], 8;"
                 :: "r"(saddr), "l"(g) : "memory");
}
#define CPA_COMMIT() asm volatile("cp.async.commit_group;":::"memory")
#define CPA_WAIT(n)  asm volatile("cp.async.wait_group %0;"::"n"(n):"memory")

#define NEG1C 0xBF800000BF800000ULL  /* (-1.f,-1.f) */

__device__ __forceinline__ u64 cmul2(u64 v, ulonglong2 w){
    return fma2(swp2(v), w.y, mul2(v, w.x));
}

// ---------------------------------------------------------------------------
__global__ void k_init(){
    int j = threadIdx.x;                 // 128 threads
    double a = (double)j * (3.14159265358979323846/64.0);
    float c = (float)cos(a), s = (float)sin(a);
    g_twF[2*j]   = pk2(c,c);  g_twF[2*j+1] = pk2(s,-s);
    g_twI[2*j]   = pk2(c,c);  g_twI[2*j+1] = pk2(-s,s);
}

// ---------------------------------------------------------------------------
// In-smem 128-point radix-2 DIF FFT with fused stage pairs (bit-identical to
// the sequential radix-2 version). xs[128 pts][64 cols] u64 packed complex.
// 512 threads: c = tid&63, tg = tid>>6 (8 groups x 4 quads per fused pass).
__device__ __forceinline__ void fft128(u64* xs, const ulonglong2* tws,
                                       int c, int tg){
    #pragma unroll 1
    for(int lm=6; lm>=2; lm-=2){
        int m = 1<<lm, hm = m>>1;
        #pragma unroll
        for(int u=0; u<4; u++){
            int q = tg*4+u;                 // 0..31 quads
            int j = q & (hm-1);
            int blk = q >> (lm-1);
            int i0 = blk*2*m + j;
            u64 a = xs[i0*64+c],       b = xs[(i0+hm)*64+c];
            u64 d = xs[(i0+m)*64+c],   e = xs[(i0+m+hm)*64+c];
            int eA = j<<(6-lm);
            ulonglong2 wA  = tws[eA];
            ulonglong2 wA2 = tws[eA+32];
            ulonglong2 wB  = tws[2*eA];
            u64 s0 = add2(a,d), d0 = fma2(d,NEG1C,a);
            u64 s1 = add2(b,e), d1 = fma2(e,NEG1C,b);
            u64 r0 = cmul2(d0, wA);
            u64 r1 = cmul2(d1, wA2);
            xs[i0*64+c]        = add2(s0,s1);
            xs[(i0+hm)*64+c]   = cmul2(fma2(s1,NEG1C,s0), wB);
            xs[(i0+m)*64+c]    = add2(r0,r1);
            xs[(i0+m+hm)*64+c] = cmul2(fma2(r1,NEG1C,r0), wB);
        }
        __syncthreads();
    }
    // final stage (m=1), twiddle = 1
    #pragma unroll
    for(int u=0; u<8; u++){
        int t = tg*8+u;                     // 0..63 pairs
        int i1 = 2*t;
        u64 a = xs[i1*64+c], b = xs[(i1+1)*64+c];
        xs[i1*64+c]     = add2(a,b);
        xs[(i1+1)*64+c] = fma2(b,NEG1C,a);
    }
    __syncthreads();
}

#define FFT_SMEM (65536 + 1024)

// ---------------------------------------------------------------------------
// Stage 1: rfft along W, two real channels packed per complex FFT.
__global__ void __launch_bounds__(512) k_s1(const float* __restrict__ x){
    extern __shared__ __align__(16) char smraw[];
    u64* xs = (u64*)smraw;                       // [128][64]
    ulonglong2* tws = (ulonglong2*)(smraw + 65536);
    int tid = threadIdx.x, c = tid&63, tg = tid>>6;
    int bh = blockIdx.x, cb = blockIdx.y*128;
    const float* xin = x + (size_t)bh*(WN*CN) + cb;
    for(int i=tid;i<8192;i+=512){
        int w=i>>6, cc=i&63;
        float2 v = *(const float2*)&xin[(size_t)w*CN + 2*cc];
        xs[i] = pk2(v.x, v.y);
    }
    if(tid<64) tws[tid] = *(const ulonglong2*)&g_twF[2*tid];
    __syncthreads();
    fft128(xs, tws, c, tg);

    // unscramble: Xc = (Z[k]+conj(Z[-k]))/2 ; Xd = -i(Z[k]-conj(Z[-k]))/2
    u64* ob = g_A + (size_t)bh*ROWST + cb;
    const float sc = 1.0f/256.0f;   // 0.5 * (1/128 ortho)
    for(int k=tg; k<65; k+=8){
        int s1 = __brev(k)>>25;
        int s2 = __brev((128-k)&127)>>25;
        u64 Z = xs[s1*64+c], Zm = xs[s2*64+c];
        float a,b,p,q; upk2(Z,a,b); upk2(Zm,p,q);
        ulonglong2 st;
        st.x = pk2(sc*(a+p), sc*(b-q));
        st.y = pk2(sc*(b+q), sc*(p-a));
        *(ulonglong2*)&ob[(size_t)k*CN + 2*c] = st;
    }
}

// ---------------------------------------------------------------------------
// Stage 2/4: complex FFT along H. dir=0: fwd g_A->g_B. dir=1: inv g_B->g_A.
__global__ void __launch_bounds__(512) k_ffth(int dir){
    extern __shared__ __align__(16) char smraw[];
    u64* xs = (u64*)smraw;
    ulonglong2* tws = (ulonglong2*)(smraw + 65536);
    int tid = threadIdx.x, c = tid&63, tg = tid>>6;
    int b = blockIdx.x / WFQ, wf = blockIdx.x % WFQ;
    int cb = blockIdx.y*64;
    const u64* in = dir ? g_B : g_A;
    u64* out      = dir ? g_A : g_B;
    size_t base = (size_t)b*HN*ROWST + (size_t)wf*CN + cb;

    for(int i=tid;i<4096;i+=512){
        int h=i>>5, cp=i&31;
        ulonglong2 v = *(const ulonglong2*)(in + base + (size_t)h*ROWST + 2*cp);
        *(ulonglong2*)&xs[h*64 + 2*cp] = v;
    }
    if(tid<64) tws[tid] = *(const ulonglong2*)(dir ? &g_twI[2*tid] : &g_twF[2*tid]);
    __syncthreads();
    fft128(xs, tws, c, tg);

    for(int s=tid;s<4096;s+=512){
        int islot=s>>5, cp=s&31;
        int k = __brev(islot)>>25;
        ulonglong2 v = *(const ulonglong2*)&xs[islot*64 + 2*cp];
        *(ulonglong2*)(out + base + (size_t)k*ROWST + 2*cp) = v;
    }
}

// ---------------------------------------------------------------------------
// Stage 3: one complex block-diagonal MLP layer with softshrink.
// R10 structure (2pt x 12out, 2 CTAs/SM, cp.async double-buffered x) with the
// GAUSS 3-multiply complex trick: weight planes p1=wr, p2=wi-wr, p3=wr+wi;
// A1 += (a+b)p1, A2 += a*p2, A3 += b*p3; re=A1-A3, im=A1+A2. 36 fma2 per
// thread per i instead of 48 (25% lower fma-pipe floor). Bias folded into
// A2/A3 init. 4 chunks of 24 i.
// grid (260 point-tiles of 128, 16 = 8 kb x 2 output-halves of 48). 256 thr.
#define MLP_XS0   0
#define MLP_XS1   24960
#define MLP_W1    49920
#define MLP_W2    68352
#define MLP_W3    86784
#define MLP_BS    105216
#define MLP_SMEM  105600
__global__ void __launch_bounds__(256,2) k_mlp(int which, const float* __restrict__ w,
                                               const float* __restrict__ bvec){
    extern __shared__ __align__(16) char smraw[];
    u64* xbuf[2];
    xbuf[0] = (u64*)(smraw + MLP_XS0);           // [24 i][130 p]
    xbuf[1] = (u64*)(smraw + MLP_XS1);
    float*  w1s = (float*)(smraw + MLP_W1);      // [96 i][48 o]  wr
    float*  w2s = (float*)(smraw + MLP_W2);      //               wi-wr
    float*  w3s = (float*)(smraw + MLP_W3);      //               wr+wi
    float2* bs  = (float2*)(smraw + MLP_BS);
    u32 smb = smem_u32(smraw);
    int tid = threadIdx.x;
    int P0 = blockIdx.x*128;
    int kb = blockIdx.y & 7, o0 = (blockIdx.y>>3)*48;
    const u64* in = which ? g_A : g_B;
    u64* out      = which ? g_B : g_A;
    const u64* inb = in + (size_t)P0*CN + kb*96;

    // prefetch chunk 0 (24 i x 128 p)
    for(int n=tid;n<3072;n+=256){
        int p = n/24, i = n - p*24;
        cpa8(smb + MLP_XS0 + (u32)(i*130+p)*8, inb + (size_t)p*CN + i);
    }
    CPA_COMMIT();

    for(int t=tid;t<4608;t+=256){
        int i = t/48, oo = t - i*48;
        float wr = w[(size_t)kb*9216 + i*96 + o0 + oo];
        float wi = w[(size_t)(8+kb)*9216 + i*96 + o0 + oo];
        w1s[t] = wr;
        w2s[t] = wi - wr;
        w3s[t] = wr + wi;
    }
    if(tid<48) bs[tid] = make_float2(bvec[kb*96 + o0 + tid],
                                     bvec[768 + kb*96 + o0 + tid]);
    __syncthreads();     // weights+bias visible

    int pl = tid&63, og = tid>>6, ob = og*12;
    u64 A1[2][6], A2[2][6], A3[2][6];
    #pragma unroll
    for(int k=0;k<6;k++){
        float2 b0 = bs[ob+2*k], b1 = bs[ob+2*k+1];
        u64 bi = pk2(b0.y,b1.y);          // +im bias
        u64 nbr = pk2(-b0.x,-b1.x);       // -re bias (re = A1 - A3)
        A1[0][k]=0ull; A2[0][k]=bi; A3[0][k]=nbr;
        A1[1][k]=0ull; A2[1][k]=bi; A3[1][k]=nbr;
    }

    #pragma unroll 1
    for(int ch=0; ch<4; ch++){
        // prefetch next chunk into the other buffer (overlaps compute below)
        if(ch<3){
            u32 dst = smb + ((ch+1)&1 ? MLP_XS1 : MLP_XS0);
            const u64* src = inb + (ch+1)*24;
            for(int n=tid;n<3072;n+=256){
                int p = n/24, i = n - p*24;
                cpa8(dst + (u32)(i*130+p)*8, src + (size_t)p*CN + i);
            }
            CPA_COMMIT();
            CPA_WAIT(1);          // chunk ch landed
        } else {
            CPA_WAIT(0);
        }
        __syncthreads();

        const u64* xsb = xbuf[ch&1];
        const float* w1b = w1s + (ch*24)*48 + ob;
        const float* w2b = w2s + (ch*24)*48 + ob;
        const float* w3b = w3s + (ch*24)*48 + ob;
        #pragma unroll 2
        for(int i=0;i<24;i++){
            ulonglong2 xv = *(const ulonglong2*)&xsb[i*130 + 2*pl];
            const ulonglong2* p1p = (const ulonglong2*)(w1b + i*48);
            const ulonglong2* p2p = (const ulonglong2*)(w2b + i*48);
            const ulonglong2* p3p = (const ulonglong2*)(w3b + i*48);
            ulonglong2 qa = p1p[0], qb = p1p[1], qc = p1p[2];
            ulonglong2 ra = p2p[0], rb = p2p[1], rc = p2p[2];
            ulonglong2 sa = p3p[0], sb = p3p[1], sc = p3p[2];
            u64 p1r[6], p2r[6], p3r[6];
            p1r[0]=qa.x; p1r[1]=qa.y; p1r[2]=qb.x; p1r[3]=qb.y; p1r[4]=qc.x; p1r[5]=qc.y;
            p2r[0]=ra.x; p2r[1]=ra.y; p2r[2]=rb.x; p2r[3]=rb.y; p2r[4]=rc.x; p2r[5]=rc.y;
            p3r[0]=sa.x; p3r[1]=sa.y; p3r[2]=sb.x; p3r[3]=sb.y; p3r[4]=sc.x; p3r[5]=sc.y;
            #pragma unroll
            for(int t=0;t<2;t++){
                u64 xvt = t ? xv.y : xv.x;
                float a,b; upk2(xvt,a,b);
                float s = a+b;
                u64 sab=pk2(s,s), spa=pk2(a,a), spb=pk2(b,b);
                #pragma unroll
                for(int k=0;k<6;k++){
                    A1[t][k]=fma2(sab, p1r[k], A1[t][k]);
                    A2[t][k]=fma2(spa, p2r[k], A2[t][k]);
                    A3[t][k]=fma2(spb, p3r[k], A3[t][k]);
                }
            }
        }
        __syncthreads();   // compute(ch) done before buffer reuse next iter
    }

    u64* obp = out + (size_t)(P0 + 2*pl)*CN + kb*96 + o0 + ob;
    #pragma unroll
    for(int t=0;t<2;t++){
        u64* op = obp + (size_t)t*CN;
        #pragma unroll
        for(int k=0;k<3;k++){
            u64 reA = fma2(A3[t][2*k],  NEG1C, A1[t][2*k]);    // A1-A3 (+br)
            u64 imA = add2(A1[t][2*k],  A2[t][2*k]);           // A1+A2 (+bi)
            u64 reB = fma2(A3[t][2*k+1],NEG1C, A1[t][2*k+1]);
            u64 imB = add2(A1[t][2*k+1],A2[t][2*k+1]);
            float r0,r1,i0,i1,r2,r3,i2,i3;
            upk2(reA,r0,r1); upk2(imA,i0,i1);
            upk2(reB,r2,r3); upk2(imB,i2,i3);
            ulonglong2 s0, s1;
            s0.x = pk2(sshrink(r0), sshrink(i0));
            s0.y = pk2(sshrink(r1), sshrink(i1));
            s1.x = pk2(sshrink(r2), sshrink(i2));
            s1.y = pk2(sshrink(r3), sshrink(i3));
            *(ulonglong2*)(op + 4*k)     = s0;
            *(ulonglong2*)(op + 4*k + 2) = s1;
        }
    }
}

// ---------------------------------------------------------------------------
// Stage 5: irfft along W + residual, two real outputs packed per complex FFT.
__global__ void __launch_bounds__(512) k_s5(const float* __restrict__ x,
                                            float* __restrict__ y){
    extern __shared__ __align__(16) char smraw[];
    u64* xs = (u64*)smraw;
    ulonglong2* tws = (ulonglong2*)(smraw + 65536);
    int tid = threadIdx.x, c = tid&63, tg = tid>>6;
    int bh = blockIdx.x, cb = blockIdx.y*128;
    const u64* in = g_A + (size_t)bh*ROWST + cb;
    const float sc = 1.0f/128.0f;   // inverse ortho total

    // Build paired spectrum Z[k] = Xc[k] + i*Xd[k], hermitian-extended.
    // pocketfft C2R ignores Im at DC/Nyquist -> zero them.
    for(int t=tid;t<65*64;t+=512){
        int k=t>>6, cc=t&63;
        ulonglong2 v = *(const ulonglong2*)&in[(size_t)k*CN + 2*cc];
        float cr,ci,dr,di; upk2(v.x,cr,ci); upk2(v.y,dr,di);
        if(k==0 || k==64){ ci = 0.0f; di = 0.0f; }
        xs[k*64+cc] = pk2(sc*(cr-di), sc*(ci+dr));
        if(k>=1 && k<=63)
            xs[(128-k)*64+cc] = pk2(sc*(cr+di), sc*(dr-ci));
    }
    if(tid<64) tws[tid] = *(const ulonglong2*)&g_twI[2*tid];
    __syncthreads();
    fft128(xs, tws, c, tg);   // inverse (e^{+i}), unnormalized

    size_t obase = (size_t)bh*(WN*CN) + cb;
    for(int s=tid;s<8192;s+=512){
        int islot=s>>6, cc=s&63;
        int w = __brev(islot)>>25;
        float yr,yi; upk2(xs[s], yr, yi);
        size_t off = obase + (size_t)w*CN + 2*cc;
        float2 bv = *(const float2*)&x[off];
        *(float2*)&y[off] = make_float2(yr+bv.x, yi+bv.y);
    }
}

// ---------------------------------------------------------------------------
extern "C" void kernel_launch(void* const* d_in, const int* in_sizes, int n_in,
                              void* d_out, int out_size) {
    const float* x  = (const float*)d_in[0];
    const float* w1 = (const float*)d_in[1];
    const float* w2 = (const float*)d_in[2];
    const float* b1 = (const float*)d_in[3];
    const float* b2 = (const float*)d_in[4];
    float* y = (float*)d_out;

    cudaFuncSetAttribute(k_s1,   cudaFuncAttributeMaxDynamicSharedMemorySize, FFT_SMEM);
    cudaFuncSetAttribute(k_ffth, cudaFuncAttributeMaxDynamicSharedMemorySize, FFT_SMEM);
    cudaFuncSetAttribute(k_s5,   cudaFuncAttributeMaxDynamicSharedMemorySize, FFT_SMEM);
    cudaFuncSetAttribute(k_mlp,  cudaFuncAttributeMaxDynamicSharedMemorySize, MLP_SMEM);

    k_init<<<1,128>>>();
    k_s1  <<<dim3(512,6), 512, FFT_SMEM>>>(x);
    k_ffth<<<dim3(260,12),512, FFT_SMEM>>>(0);
    k_mlp <<<dim3(260,16),256, MLP_SMEM>>>(0, w1, b1);
    k_mlp <<<dim3(260,16),256, MLP_SMEM>>>(1, w2, b2);
    k_ffth<<<dim3(260,12),512, FFT_SMEM>>>(1);
    k_s5  <<<dim3(512,6), 512, FFT_SMEM>>>(x, y);
    (void)in_sizes; (void)n_in; (void)out_size;
}

// round 15
// speedup vs baseline: 1.0435x; 1.0435x over previous
#include <cuda_runtime.h>
#include <math.h>

typedef unsigned long long u64;
typedef unsigned int u32;

#define BN 4
#define HN 128
#define WN 128
#define CN 768
#define WFQ 65
#define ROWST (WFQ*CN)              /* 49920 u64 per (b,h) row */
#define NELEM (BN*HN*WFQ*CN)        /* 25,559,040 complex */

// Scratch complex buffers (re = low 32 bits, im = high 32 bits)
__device__ __align__(128) u64 g_A[NELEM];
__device__ __align__(128) u64 g_B[NELEM];
// Twiddle tables (128th roots of unity), cmul-ready pairs
__device__ __align__(16) u64 g_twF[256];   // pairs (c,c),(s,-s)   fwd  e^{-i}
__device__ __align__(16) u64 g_twI[256];   // pairs (c,c),(-s,s)   inv  e^{+i}

__device__ __forceinline__ u64 pk2(float lo, float hi){
    u64 r; asm("mov.b64 %0,{%1,%2};":"=l"(r):"f"(lo),"f"(hi)); return r;
}
__device__ __forceinline__ void upk2(u64 v, float& lo, float& hi){
    asm("mov.b64 {%0,%1},%2;":"=f"(lo),"=f"(hi):"l"(v));
}
__device__ __forceinline__ u64 fma2(u64 a, u64 b, u64 c){
    u64 d; asm("fma.rn.f32x2 %0,%1,%2,%3;":"=l"(d):"l"(a),"l"(b),"l"(c)); return d;
}
__device__ __forceinline__ u64 mul2(u64 a, u64 b){
    u64 d; asm("mul.rn.f32x2 %0,%1,%2;":"=l"(d):"l"(a),"l"(b)); return d;
}
__device__ __forceinline__ u64 add2(u64 a, u64 b){
    u64 d; asm("add.rn.f32x2 %0,%1,%2;":"=l"(d):"l"(a),"l"(b)); return d;
}
__device__ __forceinline__ u64 swp2(u64 v){
    float lo,hi; upk2(v,lo,hi); return pk2(hi,lo);
}
__device__ __forceinline__ float sshrink(float v){
    return copysignf(fmaxf(fabsf(v)-0.01f,0.0f), v);
}
__device__ __forceinline__ u32 smem_u32(const void* p){
    u32 a; asm("{ .reg .u64 t; cvta.to.shared.u64 t, %1; cvt.u32.u64 %0, t; }"
               : "=r"(a) : "l"(p)); return a;
}
__device__ __forceinline__ void cpa8(u32 saddr, const void* g){
    asm volatile("cp.async.ca.shared.global [%0], [%1], 8;"
                 :: "r"(saddr), "l"(g) : "memory");
}
#define CPA_COMMIT() asm volatile("cp.async.commit_group;":::"memory")
#define CPA_WAIT(n)  asm volatile("cp.async.wait_group %0;"::"n"(n):"memory")

#define NEG1C 0xBF800000BF800000ULL  /* (-1.f,-1.f) */

__device__ __forceinline__ u64 cmul2(u64 v, ulonglong2 w){
    return fma2(swp2(v), w.y, mul2(v, w.x));
}

// ---------------------------------------------------------------------------
__global__ void k_init(){
    int j = threadIdx.x;                 // 128 threads
    double a = (double)j * (3.14159265358979323846/64.0);
    float c = (float)cos(a), s = (float)sin(a);
    g_twF[2*j]   = pk2(c,c);  g_twF[2*j+1] = pk2(s,-s);
    g_twI[2*j]   = pk2(c,c);  g_twI[2*j+1] = pk2(-s,s);
}

// ---------------------------------------------------------------------------
// In-smem 128-point radix-2 DIF FFT, 3 passes (bit-identical butterflies):
//   pass lm=6: stages 6,5 fused (smem quads)
//   pass lm=4: stages 4,3 fused (smem quads)
//   tail: stages 2,1,0 fused entirely in registers on 8-point blocks.
// xs[128 pts][64 cols] u64 packed complex. 512 threads: c=tid&63, tg=tid>>6.
// On exit, slot i holds X[bitrev7(i)].
__device__ __forceinline__ void fft128(u64* xs, const ulonglong2* tws,
                                       int c, int tg){
    #pragma unroll
    for(int lm=6; lm>=4; lm-=2){
        int m = 1<<lm, hm = m>>1;
        #pragma unroll
        for(int u=0; u<4; u++){
            int q = tg*4+u;                 // 0..31 quads
            int j = q & (hm-1);
            int blk = q >> (lm-1);
            int i0 = blk*2*m + j;
            u64 a = xs[i0*64+c],       b = xs[(i0+hm)*64+c];
            u64 d = xs[(i0+m)*64+c],   e = xs[(i0+m+hm)*64+c];
            int eA = j<<(6-lm);
            ulonglong2 wA  = tws[eA];
            ulonglong2 wA2 = tws[eA+32];
            ulonglong2 wB  = tws[2*eA];
            u64 s0 = add2(a,d), d0 = fma2(d,NEG1C,a);
            u64 s1 = add2(b,e), d1 = fma2(e,NEG1C,b);
            u64 r0 = cmul2(d0, wA);
            u64 r1 = cmul2(d1, wA2);
            xs[i0*64+c]        = add2(s0,s1);
            xs[(i0+hm)*64+c]   = cmul2(fma2(s1,NEG1C,s0), wB);
            xs[(i0+m)*64+c]    = add2(r0,r1);
            xs[(i0+m+hm)*64+c] = cmul2(fma2(r1,NEG1C,r0), wB);
        }
        __syncthreads();
    }
    // tail: stages 2,1,0 on 8-point register blocks (16 blocks, 2 per tg)
    #pragma unroll
    for(int u=0; u<2; u++){
        int i0 = (tg*2+u)*8;
        u64 v[8];
        #pragma unroll
        for(int k=0;k<8;k++) v[k] = xs[(i0+k)*64+c];
        // stage lm=2 (m=4): pairs (k, k+4), tw = tws[k<<4]
        #pragma unroll
        for(int k=0;k<4;k++){
            u64 s = add2(v[k], v[k+4]);
            u64 d = cmul2(fma2(v[k+4],NEG1C,v[k]), tws[k<<4]);
            v[k] = s; v[k+4] = d;
        }
        // stage lm=1 (m=2): pairs (h+k, h+k+2), tw = tws[k<<5]
        #pragma unroll
        for(int h=0;h<8;h+=4){
            #pragma unroll
            for(int k=0;k<2;k++){
                u64 a = v[h+k], b = v[h+k+2];
                u64 s = add2(a,b);
                u64 d = cmul2(fma2(b,NEG1C,a), tws[k<<5]);
                v[h+k] = s; v[h+k+2] = d;
            }
        }
        // stage lm=0 (m=1): pairs (k,k+1), tw = 1
        #pragma unroll
        for(int k=0;k<8;k+=2){
            u64 a = v[k], b = v[k+1];
            v[k]   = add2(a,b);
            v[k+1] = fma2(b,NEG1C,a);
        }
        #pragma unroll
        for(int k=0;k<8;k++) xs[(i0+k)*64+c] = v[k];
    }
    __syncthreads();
}

#define FFT_SMEM (65536 + 1024)

// ---------------------------------------------------------------------------
// Stage 1: rfft along W, two real channels packed per complex FFT.
__global__ void __launch_bounds__(512) k_s1(const float* __restrict__ x){
    extern __shared__ __align__(16) char smraw[];
    u64* xs = (u64*)smraw;                       // [128][64]
    ulonglong2* tws = (ulonglong2*)(smraw + 65536);
    int tid = threadIdx.x, c = tid&63, tg = tid>>6;
    int bh = blockIdx.x, cb = blockIdx.y*128;
    const float* xin = x + (size_t)bh*(WN*CN) + cb;
    for(int i=tid;i<8192;i+=512){
        int w=i>>6, cc=i&63;
        float2 v = *(const float2*)&xin[(size_t)w*CN + 2*cc];
        xs[i] = pk2(v.x, v.y);
    }
    if(tid<64) tws[tid] = *(const ulonglong2*)&g_twF[2*tid];
    __syncthreads();
    fft128(xs, tws, c, tg);

    // unscramble: Xc = (Z[k]+conj(Z[-k]))/2 ; Xd = -i(Z[k]-conj(Z[-k]))/2
    u64* ob = g_A + (size_t)bh*ROWST + cb;
    const float sc = 1.0f/256.0f;   // 0.5 * (1/128 ortho)
    for(int k=tg; k<65; k+=8){
        int s1 = __brev(k)>>25;
        int s2 = __brev((128-k)&127)>>25;
        u64 Z = xs[s1*64+c], Zm = xs[s2*64+c];
        float a,b,p,q; upk2(Z,a,b); upk2(Zm,p,q);
        ulonglong2 st;
        st.x = pk2(sc*(a+p), sc*(b-q));
        st.y = pk2(sc*(b+q), sc*(p-a));
        *(ulonglong2*)&ob[(size_t)k*CN + 2*c] = st;
    }
}

// ---------------------------------------------------------------------------
// Stage 2/4: complex FFT along H. dir=0: fwd g_A->g_B. dir=1: inv g_B->g_A.
__global__ void __launch_bounds__(512) k_ffth(int dir){
    extern __shared__ __align__(16) char smraw[];
    u64* xs = (u64*)smraw;
    ulonglong2* tws = (ulonglong2*)(smraw + 65536);
    int tid = threadIdx.x, c = tid&63, tg = tid>>6;
    int b = blockIdx.x / WFQ, wf = blockIdx.x % WFQ;
    int cb = blockIdx.y*64;
    const u64* in = dir ? g_B : g_A;
    u64* out      = dir ? g_A : g_B;
    size_t base = (size_t)b*HN*ROWST + (size_t)wf*CN + cb;

    for(int i=tid;i<4096;i+=512){
        int h=i>>5, cp=i&31;
        ulonglong2 v = *(const ulonglong2*)(in + base + (size_t)h*ROWST + 2*cp);
        *(ulonglong2*)&xs[h*64 + 2*cp] = v;
    }
    if(tid<64) tws[tid] = *(const ulonglong2*)(dir ? &g_twI[2*tid] : &g_twF[2*tid]);
    __syncthreads();
    fft128(xs, tws, c, tg);

    for(int s=tid;s<4096;s+=512){
        int islot=s>>5, cp=s&31;
        int k = __brev(islot)>>25;
        ulonglong2 v = *(const ulonglong2*)&xs[islot*64 + 2*cp];
        *(ulonglong2*)(out + base + (size_t)k*ROWST + 2*cp) = v;
    }
}

// ---------------------------------------------------------------------------
// Stage 3: one complex block-diagonal MLP layer with softshrink.
// (R10 variant verbatim — best measured: 455us.) 2pt x 12out per thread,
// cp.async double-buffered x chunks [32 i][130 p], 2 CTAs/SM.
// grid (260 point-tiles of 128, 16 = 8 kb x 2 output-halves of 48). 256 thr.
#define MLP_XS0   0
#define MLP_XS1   33280
#define MLP_WR    66560
#define MLP_WI    84992
#define MLP_BS    103424
#define MLP_SMEM  103936
__global__ void __launch_bounds__(256,2) k_mlp(int which, const float* __restrict__ w,
                                               const float* __restrict__ bvec){
    extern __shared__ __align__(16) char smraw[];
    u64*    xbuf[2];
    xbuf[0] = (u64*)(smraw + MLP_XS0);           // [32 i][130 p]
    xbuf[1] = (u64*)(smraw + MLP_XS1);
    float*  wr_s = (float*)(smraw + MLP_WR);     // [96 i][48 o]
    float*  wi_s = (float*)(smraw + MLP_WI);
    float2* bs   = (float2*)(smraw + MLP_BS);
    u32 smb = smem_u32(smraw);
    int tid = threadIdx.x;
    int P0 = blockIdx.x*128;
    int kb = blockIdx.y & 7, o0 = (blockIdx.y>>3)*48;
    const u64* in = which ? g_A : g_B;
    u64* out      = which ? g_B : g_A;
    const u64* inb = in + (size_t)P0*CN + kb*96;

    // prefetch chunk 0
    for(int n=tid;n<4096;n+=256){
        int p = n>>5, i = n&31;
        cpa8(smb + MLP_XS0 + (u32)(i*130+p)*8, inb + (size_t)p*CN + i);
    }
    CPA_COMMIT();

    for(int t=tid;t<4608;t+=256){
        int i = t/48, oo = t - i*48;
        wr_s[t] = w[(size_t)kb*9216 + i*96 + o0 + oo];
        wi_s[t] = w[(size_t)(8+kb)*9216 + i*96 + o0 + oo];
    }
    if(tid<48) bs[tid] = make_float2(bvec[kb*96 + o0 + tid],
                                     bvec[768 + kb*96 + o0 + tid]);
    __syncthreads();     // weights+bias visible

    int pl = tid&63, og = tid>>6, ob = og*12;
    u64 are[2][6], aim[2][6];
    #pragma unroll
    for(int k=0;k<6;k++){
        float2 b0 = bs[ob+2*k], b1 = bs[ob+2*k+1];
        u64 r = pk2(b0.x,b1.x), m = pk2(b0.y,b1.y);
        are[0][k]=r; aim[0][k]=m;
        are[1][k]=r; aim[1][k]=m;
    }

    #pragma unroll 1
    for(int ch=0; ch<3; ch++){
        // prefetch next chunk into the other buffer (overlaps compute below)
        if(ch<2){
            u32 dst = smb + ((ch+1)&1 ? MLP_XS1 : MLP_XS0);
            const u64* src = inb + (ch+1)*32;
            for(int n=tid;n<4096;n+=256){
                int p = n>>5, i = n&31;
                cpa8(dst + (u32)(i*130+p)*8, src + (size_t)p*CN + i);
            }
            CPA_COMMIT();
            CPA_WAIT(1);          // chunk ch landed
        } else {
            CPA_WAIT(0);
        }
        __syncthreads();

        const u64* xsb = xbuf[ch&1];
        const float* wrb = wr_s + (ch*32)*48 + ob;
        const float* wib = wi_s + (ch*32)*48 + ob;
        #pragma unroll 2
        for(int i=0;i<32;i++){
            ulonglong2 xv = *(const ulonglong2*)&xsb[i*130 + 2*pl];
            const ulonglong2* wrp = (const ulonglong2*)(wrb + i*48);
            const ulonglong2* wip = (const ulonglong2*)(wib + i*48);
            ulonglong2 wa = wrp[0], wb = wrp[1], wc = wrp[2];
            ulonglong2 va = wip[0], vb = wip[1], vc = wip[2];
            u64 wreg[6]; u64 vreg[6];
            wreg[0]=wa.x; wreg[1]=wa.y; wreg[2]=wb.x; wreg[3]=wb.y; wreg[4]=wc.x; wreg[5]=wc.y;
            vreg[0]=va.x; vreg[1]=va.y; vreg[2]=vb.x; vreg[3]=vb.y; vreg[4]=vc.x; vreg[5]=vc.y;
            #pragma unroll
            for(int t=0;t<2;t++){
                u64 xvt = t ? xv.y : xv.x;
                float xr,xi; upk2(xvt,xr,xi);
                u64 rr=pk2(xr,xr), iv=pk2(xi,xi), nii=pk2(-xi,-xi);
                #pragma unroll
                for(int k=0;k<6;k++){
                    are[t][k]=fma2(rr, wreg[k],are[t][k]);
                    are[t][k]=fma2(nii,vreg[k],are[t][k]);
                    aim[t][k]=fma2(iv, wreg[k],aim[t][k]);
                    aim[t][k]=fma2(rr, vreg[k],aim[t][k]);
                }
            }
        }
        __syncthreads();   // compute(ch) done before buffer reuse next iter
    }

    u64* obp = out + (size_t)(P0 + 2*pl)*CN + kb*96 + o0 + ob;
    #pragma unroll
    for(int t=0;t<2;t++){
        u64* op = obp + (size_t)t*CN;
        #pragma unroll
        for(int k=0;k<3;k++){
            float r0,r1,i0,i1,r2,r3,i2,i3;
            upk2(are[t][2*k],  r0,r1); upk2(aim[t][2*k],  i0,i1);
            upk2(are[t][2*k+1],r2,r3); upk2(aim[t][2*k+1],i2,i3);
            ulonglong2 s0, s1;
            s0.x = pk2(sshrink(r0), sshrink(i0));
            s0.y = pk2(sshrink(r1), sshrink(i1));
            s1.x = pk2(sshrink(r2), sshrink(i2));
            s1.y = pk2(sshrink(r3), sshrink(i3));
            *(ulonglong2*)(op + 4*k)     = s0;
            *(ulonglong2*)(op + 4*k + 2) = s1;
        }
    }
}

// ---------------------------------------------------------------------------
// Stage 5: irfft along W + residual, two real outputs packed per complex FFT.
__global__ void __launch_bounds__(512) k_s5(const float* __restrict__ x,
                                            float* __restrict__ y){
    extern __shared__ __align__(16) char smraw[];
    u64* xs = (u64*)smraw;
    ulonglong2* tws = (ulonglong2*)(smraw + 65536);
    int tid = threadIdx.x, c = tid&63, tg = tid>>6;
    int bh = blockIdx.x, cb = blockIdx.y*128;
    const u64* in = g_A + (size_t)bh*ROWST + cb;
    const float sc = 1.0f/128.0f;   // inverse ortho total

    // Build paired spectrum Z[k] = Xc[k] + i*Xd[k], hermitian-extended.
    // pocketfft C2R ignores Im at DC/Nyquist -> zero them.
    for(int t=tid;t<65*64;t+=512){
        int k=t>>6, cc=t&63;
        ulonglong2 v = *(const ulonglong2*)&in[(size_t)k*CN + 2*cc];
        float cr,ci,dr,di; upk2(v.x,cr,ci); upk2(v.y,dr,di);
        if(k==0 || k==64){ ci = 0.0f; di = 0.0f; }
        xs[k*64+cc] = pk2(sc*(cr-di), sc*(ci+dr));
        if(k>=1 && k<=63)
            xs[(128-k)*64+cc] = pk2(sc*(cr+di), sc*(dr-ci));
    }
    if(tid<64) tws[tid] = *(const ulonglong2*)&g_twI[2*tid];
    __syncthreads();
    fft128(xs, tws, c, tg);   // inverse (e^{+i}), unnormalized

    size_t obase = (size_t)bh*(WN*CN) + cb;
    for(int s=tid;s<8192;s+=512){
        int islot=s>>6, cc=s&63;
        int w = __brev(islot)>>25;
        float yr,yi; upk2(xs[s], yr, yi);
        size_t off = obase + (size_t)w*CN + 2*cc;
        float2 bv = *(const float2*)&x[off];
        *(float2*)&y[off] = make_float2(yr+bv.x, yi+bv.y);
    }
}

// ---------------------------------------------------------------------------
extern "C" void kernel_launch(void* const* d_in, const int* in_sizes, int n_in,
                              void* d_out, int out_size) {
    const float* x  = (const float*)d_in[0];
    const float* w1 = (const float*)d_in[1];
    const float* w2 = (const float*)d_in[2];
    const float* b1 = (const float*)d_in[3];
    const float* b2 = (const float*)d_in[4];
    float* y = (float*)d_out;

    cudaFuncSetAttribute(k_s1,   cudaFuncAttributeMaxDynamicSharedMemorySize, FFT_SMEM);
    cudaFuncSetAttribute(k_ffth, cudaFuncAttributeMaxDynamicSharedMemorySize, FFT_SMEM);
    cudaFuncSetAttribute(k_s5,   cudaFuncAttributeMaxDynamicSharedMemorySize, FFT_SMEM);
    cudaFuncSetAttribute(k_mlp,  cudaFuncAttributeMaxDynamicSharedMemorySize, MLP_SMEM);

    k_init<<<1,128>>>();
    k_s1  <<<dim3(512,6), 512, FFT_SMEM>>>(x);
    k_ffth<<<dim3(260,12),512, FFT_SMEM>>>(0);
    k_mlp <<<dim3(260,16),256, MLP_SMEM>>>(0, w1, b1);
    k_mlp <<<dim3(260,16),256, MLP_SMEM>>>(1, w2, b2);
    k_ffth<<<dim3(260,12),512, FFT_SMEM>>>(1);
    k_s5  <<<dim3(512,6), 512, FFT_SMEM>>>(x, y);
    (void)in_sizes; (void)n_in; (void)out_size;
}

// round 16
// speedup vs baseline: 1.0655x; 1.0210x over previous
#include <cuda_runtime.h>
#include <math.h>

typedef unsigned long long u64;
typedef unsigned int u32;

#define BN 4
#define HN 128
#define WN 128
#define CN 768
#define WFQ 65
#define ROWST (WFQ*CN)              /* 49920 u64 per (b,h) row */
#define NELEM (BN*HN*WFQ*CN)        /* 25,559,040 complex */

// Scratch complex buffers (re = low 32 bits, im = high 32 bits)
__device__ __align__(128) u64 g_A[NELEM];
__device__ __align__(128) u64 g_B[NELEM];
// Twiddle tables (128th roots of unity), cmul-ready pairs
__device__ __align__(16) u64 g_twF[256];   // pairs (c,c),(s,-s)   fwd  e^{-i}
__device__ __align__(16) u64 g_twI[256];   // pairs (c,c),(-s,s)   inv  e^{+i}

__device__ __forceinline__ u64 pk2(float lo, float hi){
    u64 r; asm("mov.b64 %0,{%1,%2};":"=l"(r):"f"(lo),"f"(hi)); return r;
}
__device__ __forceinline__ void upk2(u64 v, float& lo, float& hi){
    asm("mov.b64 {%0,%1},%2;":"=f"(lo),"=f"(hi):"l"(v));
}
__device__ __forceinline__ u64 fma2(u64 a, u64 b, u64 c){
    u64 d; asm("fma.rn.f32x2 %0,%1,%2,%3;":"=l"(d):"l"(a),"l"(b),"l"(c)); return d;
}
__device__ __forceinline__ u64 mul2(u64 a, u64 b){
    u64 d; asm("mul.rn.f32x2 %0,%1,%2;":"=l"(d):"l"(a),"l"(b)); return d;
}
__device__ __forceinline__ u64 add2(u64 a, u64 b){
    u64 d; asm("add.rn.f32x2 %0,%1,%2;":"=l"(d):"l"(a),"l"(b)); return d;
}
__device__ __forceinline__ u64 swp2(u64 v){
    float lo,hi; upk2(v,lo,hi); return pk2(hi,lo);
}
__device__ __forceinline__ float sshrink(float v){
    return copysignf(fmaxf(fabsf(v)-0.01f,0.0f), v);
}
__device__ __forceinline__ u32 smem_u32(const void* p){
    u32 a; asm("{ .reg .u64 t; cvta.to.shared.u64 t, %1; cvt.u32.u64 %0, t; }"
               : "=r"(a) : "l"(p)); return a;
}
__device__ __forceinline__ void cpa8(u32 saddr, const void* g){
    asm volatile("cp.async.ca.shared.global [%0], [%1], 8;"
                 :: "r"(saddr), "l"(g) : "memory");
}
#define CPA_COMMIT() asm volatile("cp.async.commit_group;":::"memory")
#define CPA_WAIT(n)  asm volatile("cp.async.wait_group %0;"::"n"(n):"memory")

#define NEG1C 0xBF800000BF800000ULL  /* (-1.f,-1.f) */

__device__ __forceinline__ u64 cmul2(u64 v, ulonglong2 w){
    return fma2(swp2(v), w.y, mul2(v, w.x));
}

// ---------------------------------------------------------------------------
__global__ void k_init(){
    int j = threadIdx.x;                 // 128 threads
    double a = (double)j * (3.14159265358979323846/64.0);
    float c = (float)cos(a), s = (float)sin(a);
    g_twF[2*j]   = pk2(c,c);  g_twF[2*j+1] = pk2(s,-s);
    g_twI[2*j]   = pk2(c,c);  g_twI[2*j+1] = pk2(-s,s);
}

// ---------------------------------------------------------------------------
// In-smem 128-point radix-2 DIF FFT with fused stage pairs (proven R9/R10
// version — bit-identical to sequential radix-2). xs[128 pts][64 cols].
// 512 threads: c = tid&63, tg = tid>>6 (8 groups x 4 quads per fused pass).
__device__ __forceinline__ void fft128(u64* xs, const ulonglong2* tws,
                                       int c, int tg){
    #pragma unroll 1
    for(int lm=6; lm>=2; lm-=2){
        int m = 1<<lm, hm = m>>1;
        #pragma unroll
        for(int u=0; u<4; u++){
            int q = tg*4+u;                 // 0..31 quads
            int j = q & (hm-1);
            int blk = q >> (lm-1);
            int i0 = blk*2*m + j;
            u64 a = xs[i0*64+c],       b = xs[(i0+hm)*64+c];
            u64 d = xs[(i0+m)*64+c],   e = xs[(i0+m+hm)*64+c];
            int eA = j<<(6-lm);
            ulonglong2 wA  = tws[eA];
            ulonglong2 wA2 = tws[eA+32];
            ulonglong2 wB  = tws[2*eA];
            u64 s0 = add2(a,d), d0 = fma2(d,NEG1C,a);
            u64 s1 = add2(b,e), d1 = fma2(e,NEG1C,b);
            u64 r0 = cmul2(d0, wA);
            u64 r1 = cmul2(d1, wA2);
            xs[i0*64+c]        = add2(s0,s1);
            xs[(i0+hm)*64+c]   = cmul2(fma2(s1,NEG1C,s0), wB);
            xs[(i0+m)*64+c]    = add2(r0,r1);
            xs[(i0+m+hm)*64+c] = cmul2(fma2(r1,NEG1C,r0), wB);
        }
        __syncthreads();
    }
    // final stage (m=1), twiddle = 1
    #pragma unroll
    for(int u=0; u<8; u++){
        int t = tg*8+u;                     // 0..63 pairs
        int i1 = 2*t;
        u64 a = xs[i1*64+c], b = xs[(i1+1)*64+c];
        xs[i1*64+c]     = add2(a,b);
        xs[(i1+1)*64+c] = fma2(b,NEG1C,a);
    }
    __syncthreads();
}

#define FFT_SMEM (65536 + 1024)

// ---------------------------------------------------------------------------
// Stage 1: rfft along W, two real channels packed per complex FFT.
__global__ void __launch_bounds__(512) k_s1(const float* __restrict__ x){
    extern __shared__ __align__(16) char smraw[];
    u64* xs = (u64*)smraw;                       // [128][64]
    ulonglong2* tws = (ulonglong2*)(smraw + 65536);
    int tid = threadIdx.x, c = tid&63, tg = tid>>6;
    int bh = blockIdx.x, cb = blockIdx.y*128;
    const float* xin = x + (size_t)bh*(WN*CN) + cb;
    for(int i=tid;i<8192;i+=512){
        int w=i>>6, cc=i&63;
        float2 v = *(const float2*)&xin[(size_t)w*CN + 2*cc];
        xs[i] = pk2(v.x, v.y);
    }
    if(tid<64) tws[tid] = *(const ulonglong2*)&g_twF[2*tid];
    __syncthreads();
    fft128(xs, tws, c, tg);

    // unscramble: Xc = (Z[k]+conj(Z[-k]))/2 ; Xd = -i(Z[k]-conj(Z[-k]))/2
    u64* ob = g_A + (size_t)bh*ROWST + cb;
    const float sc = 1.0f/256.0f;   // 0.5 * (1/128 ortho)
    for(int k=tg; k<65; k+=8){
        int s1 = __brev(k)>>25;
        int s2 = __brev((128-k)&127)>>25;
        u64 Z = xs[s1*64+c], Zm = xs[s2*64+c];
        float a,b,p,q; upk2(Z,a,b); upk2(Zm,p,q);
        ulonglong2 st;
        st.x = pk2(sc*(a+p), sc*(b-q));
        st.y = pk2(sc*(b+q), sc*(p-a));
        *(ulonglong2*)&ob[(size_t)k*CN + 2*c] = st;
    }
}

// ---------------------------------------------------------------------------
// Stage 2/4: complex FFT along H. dir=0: fwd g_A->g_B. dir=1: inv g_B->g_A.
__global__ void __launch_bounds__(512) k_ffth(int dir){
    extern __shared__ __align__(16) char smraw[];
    u64* xs = (u64*)smraw;
    ulonglong2* tws = (ulonglong2*)(smraw + 65536);
    int tid = threadIdx.x, c = tid&63, tg = tid>>6;
    int b = blockIdx.x / WFQ, wf = blockIdx.x % WFQ;
    int cb = blockIdx.y*64;
    const u64* in = dir ? g_B : g_A;
    u64* out      = dir ? g_A : g_B;
    size_t base = (size_t)b*HN*ROWST + (size_t)wf*CN + cb;

    for(int i=tid;i<4096;i+=512){
        int h=i>>5, cp=i&31;
        ulonglong2 v = *(const ulonglong2*)(in + base + (size_t)h*ROWST + 2*cp);
        *(ulonglong2*)&xs[h*64 + 2*cp] = v;
    }
    if(tid<64) tws[tid] = *(const ulonglong2*)(dir ? &g_twI[2*tid] : &g_twF[2*tid]);
    __syncthreads();
    fft128(xs, tws, c, tg);

    for(int s=tid;s<4096;s+=512){
        int islot=s>>5, cp=s&31;
        int k = __brev(islot)>>25;
        ulonglong2 v = *(const ulonglong2*)&xs[islot*64 + 2*cp];
        *(ulonglong2*)(out + base + (size_t)k*ROWST + 2*cp) = v;
    }
}

// ---------------------------------------------------------------------------
// Stage 3: one complex block-diagonal MLP layer with softshrink.
// R10 inner-loop shape (2 points x N outputs, packed weight pairs, cp.async
// double-buffered x) shrunk to 8 outputs/thread so THREE CTAs fit per SM
// (24 warps). Output slices of 32 per CTA; x chunks of 16 i.
// grid (260 point-tiles of 128, 24 = 8 kb x 3 output-slices of 32). 256 thr
// = 64 point-lanes x 4 output-subgroups of 8.
#define MLP_XS0   0
#define MLP_XS1   16640
#define MLP_WR    33280
#define MLP_WI    45568
#define MLP_BS    57856
#define MLP_SMEM  58368
__global__ void __launch_bounds__(256,3) k_mlp(int which, const float* __restrict__ w,
                                               const float* __restrict__ bvec){
    extern __shared__ __align__(16) char smraw[];
    u64* xbuf[2];
    xbuf[0] = (u64*)(smraw + MLP_XS0);           // [16 i][130 p]
    xbuf[1] = (u64*)(smraw + MLP_XS1);
    float*  wr_s = (float*)(smraw + MLP_WR);     // [96 i][32 o]
    float*  wi_s = (float*)(smraw + MLP_WI);
    float2* bs   = (float2*)(smraw + MLP_BS);
    u32 smb = smem_u32(smraw);
    int tid = threadIdx.x;
    int P0 = blockIdx.x*128;
    int kb = blockIdx.y & 7, o0 = (blockIdx.y>>3)*32;
    const u64* in = which ? g_A : g_B;
    u64* out      = which ? g_B : g_A;
    const u64* inb = in + (size_t)P0*CN + kb*96;

    // prefetch chunk 0 (16 i x 128 p)
    for(int n=tid;n<2048;n+=256){
        int p = n>>4, i = n&15;
        cpa8(smb + MLP_XS0 + (u32)(i*130+p)*8, inb + (size_t)p*CN + i);
    }
    CPA_COMMIT();

    for(int t=tid;t<3072;t+=256){
        int i = t>>5, oo = t&31;
        wr_s[t] = w[(size_t)kb*9216 + i*96 + o0 + oo];
        wi_s[t] = w[(size_t)(8+kb)*9216 + i*96 + o0 + oo];
    }
    if(tid<32) bs[tid] = make_float2(bvec[kb*96 + o0 + tid],
                                     bvec[768 + kb*96 + o0 + tid]);
    __syncthreads();     // weights+bias visible

    int pl = tid&63, og = tid>>6, ob = og*8;
    u64 are[2][4], aim[2][4];
    #pragma unroll
    for(int k=0;k<4;k++){
        float2 b0 = bs[ob+2*k], b1 = bs[ob+2*k+1];
        u64 r = pk2(b0.x,b1.x), m = pk2(b0.y,b1.y);
        are[0][k]=r; aim[0][k]=m;
        are[1][k]=r; aim[1][k]=m;
    }

    #pragma unroll 1
    for(int ch=0; ch<6; ch++){
        // prefetch next chunk into the other buffer (overlaps compute below)
        if(ch<5){
            u32 dst = smb + ((ch+1)&1 ? MLP_XS1 : MLP_XS0);
            const u64* src = inb + (ch+1)*16;
            for(int n=tid;n<2048;n+=256){
                int p = n>>4, i = n&15;
                cpa8(dst + (u32)(i*130+p)*8, src + (size_t)p*CN + i);
            }
            CPA_COMMIT();
            CPA_WAIT(1);          // chunk ch landed
        } else {
            CPA_WAIT(0);
        }
        __syncthreads();

        const u64* xsb = xbuf[ch&1];
        const float* wrb = wr_s + (ch*16)*32 + ob;
        const float* wib = wi_s + (ch*16)*32 + ob;
        #pragma unroll 2
        for(int i=0;i<16;i++){
            ulonglong2 xv = *(const ulonglong2*)&xsb[i*130 + 2*pl];
            const ulonglong2* wrp = (const ulonglong2*)(wrb + i*32);
            const ulonglong2* wip = (const ulonglong2*)(wib + i*32);
            ulonglong2 wa = wrp[0], wb = wrp[1];
            ulonglong2 va = wip[0], vb = wip[1];
            u64 wreg[4]; u64 vreg[4];
            wreg[0]=wa.x; wreg[1]=wa.y; wreg[2]=wb.x; wreg[3]=wb.y;
            vreg[0]=va.x; vreg[1]=va.y; vreg[2]=vb.x; vreg[3]=vb.y;
            #pragma unroll
            for(int t=0;t<2;t++){
                u64 xvt = t ? xv.y : xv.x;
                float xr,xi; upk2(xvt,xr,xi);
                u64 rr=pk2(xr,xr), iv=pk2(xi,xi), nii=pk2(-xi,-xi);
                #pragma unroll
                for(int k=0;k<4;k++){
                    are[t][k]=fma2(rr, wreg[k],are[t][k]);
                    are[t][k]=fma2(nii,vreg[k],are[t][k]);
                    aim[t][k]=fma2(iv, wreg[k],aim[t][k]);
                    aim[t][k]=fma2(rr, vreg[k],aim[t][k]);
                }
            }
        }
        __syncthreads();   // compute(ch) done before buffer reuse next iter
    }

    u64* obp = out + (size_t)(P0 + 2*pl)*CN + kb*96 + o0 + ob;
    #pragma unroll
    for(int t=0;t<2;t++){
        u64* op = obp + (size_t)t*CN;
        #pragma unroll
        for(int k=0;k<2;k++){
            float r0,r1,i0,i1,r2,r3,i2,i3;
            upk2(are[t][2*k],  r0,r1); upk2(aim[t][2*k],  i0,i1);
            upk2(are[t][2*k+1],r2,r3); upk2(aim[t][2*k+1],i2,i3);
            ulonglong2 s0, s1;
            s0.x = pk2(sshrink(r0), sshrink(i0));
            s0.y = pk2(sshrink(r1), sshrink(i1));
            s1.x = pk2(sshrink(r2), sshrink(i2));
            s1.y = pk2(sshrink(r3), sshrink(i3));
            *(ulonglong2*)(op + 4*k)     = s0;
            *(ulonglong2*)(op + 4*k + 2) = s1;
        }
    }
}

// ---------------------------------------------------------------------------
// Stage 5: irfft along W + residual, two real outputs packed per complex FFT.
__global__ void __launch_bounds__(512) k_s5(const float* __restrict__ x,
                                            float* __restrict__ y){
    extern __shared__ __align__(16) char smraw[];
    u64* xs = (u64*)smraw;
    ulonglong2* tws = (ulonglong2*)(smraw + 65536);
    int tid = threadIdx.x, c = tid&63, tg = tid>>6;
    int bh = blockIdx.x, cb = blockIdx.y*128;
    const u64* in = g_A + (size_t)bh*ROWST + cb;
    const float sc = 1.0f/128.0f;   // inverse ortho total

    // Build paired spectrum Z[k] = Xc[k] + i*Xd[k], hermitian-extended.
    // pocketfft C2R ignores Im at DC/Nyquist -> zero them.
    for(int t=tid;t<65*64;t+=512){
        int k=t>>6, cc=t&63;
        ulonglong2 v = *(const ulonglong2*)&in[(size_t)k*CN + 2*cc];
        float cr,ci,dr,di; upk2(v.x,cr,ci); upk2(v.y,dr,di);
        if(k==0 || k==64){ ci = 0.0f; di = 0.0f; }
        xs[k*64+cc] = pk2(sc*(cr-di), sc*(ci+dr));
        if(k>=1 && k<=63)
            xs[(128-k)*64+cc] = pk2(sc*(cr+di), sc*(dr-ci));
    }
    if(tid<64) tws[tid] = *(const ulonglong2*)&g_twI[2*tid];
    __syncthreads();
    fft128(xs, tws, c, tg);   // inverse (e^{+i}), unnormalized

    size_t obase = (size_t)bh*(WN*CN) + cb;
    for(int s=tid;s<8192;s+=512){
        int islot=s>>6, cc=s&63;
        int w = __brev(islot)>>25;
        float yr,yi; upk2(xs[s], yr, yi);
        size_t off = obase + (size_t)w*CN + 2*cc;
        float2 bv = *(const float2*)&x[off];
        *(float2*)&y[off] = make_float2(yr+bv.x, yi+bv.y);
    }
}

// ---------------------------------------------------------------------------
extern "C" void kernel_launch(void* const* d_in, const int* in_sizes, int n_in,
                              void* d_out, int out_size) {
    const float* x  = (const float*)d_in[0];
    const float* w1 = (const float*)d_in[1];
    const float* w2 = (const float*)d_in[2];
    const float* b1 = (const float*)d_in[3];
    const float* b2 = (const float*)d_in[4];
    float* y = (float*)d_out;

    cudaFuncSetAttribute(k_s1,   cudaFuncAttributeMaxDynamicSharedMemorySize, FFT_SMEM);
    cudaFuncSetAttribute(k_ffth, cudaFuncAttributeMaxDynamicSharedMemorySize, FFT_SMEM);
    cudaFuncSetAttribute(k_s5,   cudaFuncAttributeMaxDynamicSharedMemorySize, FFT_SMEM);
    cudaFuncSetAttribute(k_mlp,  cudaFuncAttributeMaxDynamicSharedMemorySize, MLP_SMEM);

    k_init<<<1,128>>>();
    k_s1  <<<dim3(512,6), 512, FFT_SMEM>>>(x);
    k_ffth<<<dim3(260,12),512, FFT_SMEM>>>(0);
    k_mlp <<<dim3(260,24),256, MLP_SMEM>>>(0, w1, b1);
    k_mlp <<<dim3(260,24),256, MLP_SMEM>>>(1, w2, b2);
    k_ffth<<<dim3(260,12),512, FFT_SMEM>>>(1);
    k_s5  <<<dim3(512,6), 512, FFT_SMEM>>>(x, y);
    (void)in_sizes; (void)n_in; (void)out_size;
}

// round 17
// speedup vs baseline: 1.1596x; 1.0883x over previous
#include <cuda_runtime.h>
#include <math.h>

typedef unsigned long long u64;
typedef unsigned int u32;

#define BN 4
#define HN 128
#define WN 128
#define CN 768
#define WFQ 65
#define ROWST (WFQ*CN)              /* 49920 u64 per (b,h) row */
#define NELEM (BN*HN*WFQ*CN)        /* 25,559,040 complex */

// Scratch complex buffers (re = low 32 bits, im = high 32 bits)
__device__ __align__(128) u64 g_A[NELEM];
__device__ __align__(128) u64 g_B[NELEM];
// Twiddle tables (128th roots of unity), cmul-ready pairs
__device__ __align__(16) u64 g_twF[256];   // pairs (c,c),(s,-s)   fwd  e^{-i}
__device__ __align__(16) u64 g_twI[256];   // pairs (c,c),(-s,s)   inv  e^{+i}

__device__ __forceinline__ u64 pk2(float lo, float hi){
    u64 r; asm("mov.b64 %0,{%1,%2};":"=l"(r):"f"(lo),"f"(hi)); return r;
}
__device__ __forceinline__ void upk2(u64 v, float& lo, float& hi){
    asm("mov.b64 {%0,%1},%2;":"=f"(lo),"=f"(hi):"l"(v));
}
__device__ __forceinline__ u64 fma2(u64 a, u64 b, u64 c){
    u64 d; asm("fma.rn.f32x2 %0,%1,%2,%3;":"=l"(d):"l"(a),"l"(b),"l"(c)); return d;
}
__device__ __forceinline__ u64 mul2(u64 a, u64 b){
    u64 d; asm("mul.rn.f32x2 %0,%1,%2;":"=l"(d):"l"(a),"l"(b)); return d;
}
__device__ __forceinline__ u64 add2(u64 a, u64 b){
    u64 d; asm("add.rn.f32x2 %0,%1,%2;":"=l"(d):"l"(a),"l"(b)); return d;
}
__device__ __forceinline__ u64 swp2(u64 v){
    float lo,hi; upk2(v,lo,hi); return pk2(hi,lo);
}
__device__ __forceinline__ float sshrink(float v){
    return copysignf(fmaxf(fabsf(v)-0.01f,0.0f), v);
}
__device__ __forceinline__ u32 smem_u32(const void* p){
    u32 a; asm("{ .reg .u64 t; cvta.to.shared.u64 t, %1; cvt.u32.u64 %0, t; }"
               : "=r"(a) : "l"(p)); return a;
}
__device__ __forceinline__ void cpa8(u32 saddr, const void* g){
    asm volatile("cp.async.ca.shared.global [%0], [%1], 8;"
                 :: "r"(saddr), "l"(g) : "memory");
}
#define CPA_COMMIT() asm volatile("cp.async.commit_group;":::"memory")
#define CPA_WAIT(n)  asm volatile("cp.async.wait_group %0;"::"n"(n):"memory")

#define NEG1C 0xBF800000BF800000ULL  /* (-1.f,-1.f) */

__device__ __forceinline__ u64 cmul2(u64 v, ulonglong2 w){
    return fma2(swp2(v), w.y, mul2(v, w.x));
}

// ---------------------------------------------------------------------------
__global__ void k_init(){
    int j = threadIdx.x;                 // 128 threads
    double a = (double)j * (3.14159265358979323846/64.0);
    float c = (float)cos(a), s = (float)sin(a);
    g_twF[2*j]   = pk2(c,c);  g_twF[2*j+1] = pk2(s,-s);
    g_twI[2*j]   = pk2(c,c);  g_twI[2*j+1] = pk2(-s,s);
}

// ---------------------------------------------------------------------------
// In-smem 128-point radix-2 DIF FFT with fused stage pairs (proven R9/R10
// version — bit-identical to sequential radix-2). xs[128 pts][64 cols].
// 512 threads: c = tid&63, tg = tid>>6 (8 groups x 4 quads per fused pass).
__device__ __forceinline__ void fft128(u64* xs, const ulonglong2* tws,
                                       int c, int tg){
    #pragma unroll 1
    for(int lm=6; lm>=2; lm-=2){
        int m = 1<<lm, hm = m>>1;
        #pragma unroll
        for(int u=0; u<4; u++){
            int q = tg*4+u;                 // 0..31 quads
            int j = q & (hm-1);
            int blk = q >> (lm-1);
            int i0 = blk*2*m + j;
            u64 a = xs[i0*64+c],       b = xs[(i0+hm)*64+c];
            u64 d = xs[(i0+m)*64+c],   e = xs[(i0+m+hm)*64+c];
            int eA = j<<(6-lm);
            ulonglong2 wA  = tws[eA];
            ulonglong2 wA2 = tws[eA+32];
            ulonglong2 wB  = tws[2*eA];
            u64 s0 = add2(a,d), d0 = fma2(d,NEG1C,a);
            u64 s1 = add2(b,e), d1 = fma2(e,NEG1C,b);
            u64 r0 = cmul2(d0, wA);
            u64 r1 = cmul2(d1, wA2);
            xs[i0*64+c]        = add2(s0,s1);
            xs[(i0+hm)*64+c]   = cmul2(fma2(s1,NEG1C,s0), wB);
            xs[(i0+m)*64+c]    = add2(r0,r1);
            xs[(i0+m+hm)*64+c] = cmul2(fma2(r1,NEG1C,r0), wB);
        }
        __syncthreads();
    }
    // final stage (m=1), twiddle = 1
    #pragma unroll
    for(int u=0; u<8; u++){
        int t = tg*8+u;                     // 0..63 pairs
        int i1 = 2*t;
        u64 a = xs[i1*64+c], b = xs[(i1+1)*64+c];
        xs[i1*64+c]     = add2(a,b);
        xs[(i1+1)*64+c] = fma2(b,NEG1C,a);
    }
    __syncthreads();
}

#define FFT_SMEM (65536 + 1024)

// ---------------------------------------------------------------------------
// Stage 1: rfft along W, two real channels packed per complex FFT.
__global__ void __launch_bounds__(512) k_s1(const float* __restrict__ x){
    extern __shared__ __align__(16) char smraw[];
    u64* xs = (u64*)smraw;                       // [128][64]
    ulonglong2* tws = (ulonglong2*)(smraw + 65536);
    int tid = threadIdx.x, c = tid&63, tg = tid>>6;
    int bh = blockIdx.x, cb = blockIdx.y*128;
    const float* xin = x + (size_t)bh*(WN*CN) + cb;
    for(int i=tid;i<8192;i+=512){
        int w=i>>6, cc=i&63;
        float2 v = *(const float2*)&xin[(size_t)w*CN + 2*cc];
        xs[i] = pk2(v.x, v.y);
    }
    if(tid<64) tws[tid] = *(const ulonglong2*)&g_twF[2*tid];
    __syncthreads();
    fft128(xs, tws, c, tg);

    // unscramble: Xc = (Z[k]+conj(Z[-k]))/2 ; Xd = -i(Z[k]-conj(Z[-k]))/2
    u64* ob = g_A + (size_t)bh*ROWST + cb;
    const float sc = 1.0f/256.0f;   // 0.5 * (1/128 ortho)
    for(int k=tg; k<65; k+=8){
        int s1 = __brev(k)>>25;
        int s2 = __brev((128-k)&127)>>25;
        u64 Z = xs[s1*64+c], Zm = xs[s2*64+c];
        float a,b,p,q; upk2(Z,a,b); upk2(Zm,p,q);
        ulonglong2 st;
        st.x = pk2(sc*(a+p), sc*(b-q));
        st.y = pk2(sc*(b+q), sc*(p-a));
        *(ulonglong2*)&ob[(size_t)k*CN + 2*c] = st;
    }
}

// ---------------------------------------------------------------------------
// Stage 2/4: complex FFT along H. dir=0: fwd g_A->g_B. dir=1: inv g_B->g_A.
__global__ void __launch_bounds__(512) k_ffth(int dir){
    extern __shared__ __align__(16) char smraw[];
    u64* xs = (u64*)smraw;
    ulonglong2* tws = (ulonglong2*)(smraw + 65536);
    int tid = threadIdx.x, c = tid&63, tg = tid>>6;
    int b = blockIdx.x / WFQ, wf = blockIdx.x % WFQ;
    int cb = blockIdx.y*64;
    const u64* in = dir ? g_B : g_A;
    u64* out      = dir ? g_A : g_B;
    size_t base = (size_t)b*HN*ROWST + (size_t)wf*CN + cb;

    for(int i=tid;i<4096;i+=512){
        int h=i>>5, cp=i&31;
        ulonglong2 v = *(const ulonglong2*)(in + base + (size_t)h*ROWST + 2*cp);
        *(ulonglong2*)&xs[h*64 + 2*cp] = v;
    }
    if(tid<64) tws[tid] = *(const ulonglong2*)(dir ? &g_twI[2*tid] : &g_twF[2*tid]);
    __syncthreads();
    fft128(xs, tws, c, tg);

    for(int s=tid;s<4096;s+=512){
        int islot=s>>5, cp=s&31;
        int k = __brev(islot)>>25;
        ulonglong2 v = *(const ulonglong2*)&xs[islot*64 + 2*cp];
        *(ulonglong2*)(out + base + (size_t)k*ROWST + 2*cp) = v;
    }
}

// ---------------------------------------------------------------------------
// Stage 3: BOTH complex block-diagonal MLP layers fused in one CTA.
// CTA = (128-point tile, kb). 512 thr = 64 point-pairs x 8 out-groups of 12.
// Phase A: stage x[96 i][130 p] via cp.async + W1 planes + both biases.
// Phase B: L1 accumulate (R10 inner loop), softshrink -> o1 back into the x
//          smem region (transposed, ready as L2 input); reload W2 planes.
// Phase C: L2 accumulate, softshrink, write g_B in place.
// In-place safe: each CTA reads only its own slice, fully staged before any
// write. smem 175KB -> 1 CTA/SM (16 warps), but only 3 syncs total.
#define F_XS   0
#define F_WR   99840
#define F_WI   136704
#define F_B1   173568
#define F_B2   174336
#define F_SMEM 175104
__global__ void __launch_bounds__(512,1) k_mlp2(const float* __restrict__ w1,
                                                const float* __restrict__ w2,
                                                const float* __restrict__ b1,
                                                const float* __restrict__ b2){
    extern __shared__ __align__(16) char smraw[];
    u64*    xs   = (u64*)(smraw + F_XS);         // [96 i][130 p]
    float*  wr_s = (float*)(smraw + F_WR);       // [96 i][96 o]
    float*  wi_s = (float*)(smraw + F_WI);
    float2* b1s  = (float2*)(smraw + F_B1);
    float2* b2s  = (float2*)(smraw + F_B2);
    u32 smb = smem_u32(smraw);
    int tid = threadIdx.x;
    int P0 = blockIdx.x*128, kb = blockIdx.y;
    u64* buf = g_B;                              // in/out in place
    const u64* inb = buf + (size_t)P0*CN + kb*96;

    // stage x (cp.async) — consecutive tid -> consecutive i (coalesced)
    for(int n=tid;n<12288;n+=512){
        int p = n/96, i = n - p*96;
        cpa8(smb + F_XS + (u32)(i*130+p)*8, inb + (size_t)p*CN + i);
    }
    CPA_COMMIT();
    // W1 planes ([i][o] row-major matches w layout) + biases
    for(int t=tid;t<9216;t+=512){
        wr_s[t] = w1[(size_t)kb*9216 + t];
        wi_s[t] = w1[(size_t)(8+kb)*9216 + t];
    }
    if(tid<96){
        b1s[tid] = make_float2(b1[kb*96+tid], b1[768+kb*96+tid]);
        b2s[tid] = make_float2(b2[kb*96+tid], b2[768+kb*96+tid]);
    }
    CPA_WAIT(0);
    __syncthreads();

    int pl = tid&63, og = tid>>6, ob = og*12;

    // ---- Layer 1 ----
    u64 are[2][6], aim[2][6];
    #pragma unroll
    for(int k=0;k<6;k++){
        float2 c0 = b1s[ob+2*k], c1 = b1s[ob+2*k+1];
        u64 r = pk2(c0.x,c1.x), m = pk2(c0.y,c1.y);
        are[0][k]=r; aim[0][k]=m;
        are[1][k]=r; aim[1][k]=m;
    }
    #pragma unroll 2
    for(int i=0;i<96;i++){
        ulonglong2 xv = *(const ulonglong2*)&xs[i*130 + 2*pl];
        const ulonglong2* wrp = (const ulonglong2*)&wr_s[i*96 + ob];
        const ulonglong2* wip = (const ulonglong2*)&wi_s[i*96 + ob];
        ulonglong2 wa = wrp[0], wb = wrp[1], wc = wrp[2];
        ulonglong2 va = wip[0], vb = wip[1], vc = wip[2];
        u64 wreg[6]; u64 vreg[6];
        wreg[0]=wa.x; wreg[1]=wa.y; wreg[2]=wb.x; wreg[3]=wb.y; wreg[4]=wc.x; wreg[5]=wc.y;
        vreg[0]=va.x; vreg[1]=va.y; vreg[2]=vb.x; vreg[3]=vb.y; vreg[4]=vc.x; vreg[5]=vc.y;
        #pragma unroll
        for(int t=0;t<2;t++){
            u64 xvt = t ? xv.y : xv.x;
            float xr,xi; upk2(xvt,xr,xi);
            u64 rr=pk2(xr,xr), iv=pk2(xi,xi), nii=pk2(-xi,-xi);
            #pragma unroll
            for(int k=0;k<6;k++){
                are[t][k]=fma2(rr, wreg[k],are[t][k]);
                are[t][k]=fma2(nii,vreg[k],are[t][k]);
                aim[t][k]=fma2(iv, wreg[k],aim[t][k]);
                aim[t][k]=fma2(rr, vreg[k],aim[t][k]);
            }
        }
    }
    __syncthreads();    // all xs + W1 reads done

    // o1 -> xs (transposed [o][p], same layout L2 expects) + reload W2
    #pragma unroll
    for(int k=0;k<6;k++){
        float r0,r1,i0,i1;
        upk2(are[0][k], r0, i0);   // wait — are holds (p0,p1) packing
        // repack: are[t][k] lanes are (point 2pl, 2pl+1) for output ob+?? 
        ;
    }
    // NOTE: are[t][k] packing is (out pair) per point t. Store per point:
    #pragma unroll
    for(int t=0;t<2;t++){
        #pragma unroll
        for(int k=0;k<6;k++){
            float r0,r1,i0,i1;
            upk2(are[t][k], r0, r1);   // outputs ob+2k, ob+2k+1 (re)
            upk2(aim[t][k], i0, i1);   // outputs ob+2k, ob+2k+1 (im)
            xs[(ob+2*k  )*130 + 2*pl + t] = pk2(sshrink(r0), sshrink(i0));
            xs[(ob+2*k+1)*130 + 2*pl + t] = pk2(sshrink(r1), sshrink(i1));
        }
    }
    for(int t=tid;t<9216;t+=512){
        wr_s[t] = w2[(size_t)kb*9216 + t];
        wi_s[t] = w2[(size_t)(8+kb)*9216 + t];
    }
    __syncthreads();

    // ---- Layer 2 ----
    #pragma unroll
    for(int k=0;k<6;k++){
        float2 c0 = b2s[ob+2*k], c1 = b2s[ob+2*k+1];
        u64 r = pk2(c0.x,c1.x), m = pk2(c0.y,c1.y);
        are[0][k]=r; aim[0][k]=m;
        are[1][k]=r; aim[1][k]=m;
    }
    #pragma unroll 2
    for(int i=0;i<96;i++){
        ulonglong2 xv = *(const ulonglong2*)&xs[i*130 + 2*pl];
        const ulonglong2* wrp = (const ulonglong2*)&wr_s[i*96 + ob];
        const ulonglong2* wip = (const ulonglong2*)&wi_s[i*96 + ob];
        ulonglong2 wa = wrp[0], wb = wrp[1], wc = wrp[2];
        ulonglong2 va = wip[0], vb = wip[1], vc = wip[2];
        u64 wreg[6]; u64 vreg[6];
        wreg[0]=wa.x; wreg[1]=wa.y; wreg[2]=wb.x; wreg[3]=wb.y; wreg[4]=wc.x; wreg[5]=wc.y;
        vreg[0]=va.x; vreg[1]=va.y; vreg[2]=vb.x; vreg[3]=vb.y; vreg[4]=vc.x; vreg[5]=vc.y;
        #pragma unroll
        for(int t=0;t<2;t++){
            u64 xvt = t ? xv.y : xv.x;
            float xr,xi; upk2(xvt,xr,xi);
            u64 rr=pk2(xr,xr), iv=pk2(xi,xi), nii=pk2(-xi,-xi);
            #pragma unroll
            for(int k=0;k<6;k++){
                are[t][k]=fma2(rr, wreg[k],are[t][k]);
                are[t][k]=fma2(nii,vreg[k],are[t][k]);
                aim[t][k]=fma2(iv, wreg[k],aim[t][k]);
                aim[t][k]=fma2(rr, vreg[k],aim[t][k]);
            }
        }
    }

    u64* obp = buf + (size_t)(P0 + 2*pl)*CN + kb*96 + ob;
    #pragma unroll
    for(int t=0;t<2;t++){
        u64* op = obp + (size_t)t*CN;
        #pragma unroll
        for(int k=0;k<3;k++){
            float r0,r1,i0,i1,r2,r3,i2,i3;
            upk2(are[t][2*k],  r0,r1); upk2(aim[t][2*k],  i0,i1);
            upk2(are[t][2*k+1],r2,r3); upk2(aim[t][2*k+1],i2,i3);
            ulonglong2 s0, s1;
            s0.x = pk2(sshrink(r0), sshrink(i0));
            s0.y = pk2(sshrink(r1), sshrink(i1));
            s1.x = pk2(sshrink(r2), sshrink(i2));
            s1.y = pk2(sshrink(r3), sshrink(i3));
            *(ulonglong2*)(op + 4*k)     = s0;
            *(ulonglong2*)(op + 4*k + 2) = s1;
        }
    }
}

// ---------------------------------------------------------------------------
// Stage 5: irfft along W + residual, two real outputs packed per complex FFT.
__global__ void __launch_bounds__(512) k_s5(const float* __restrict__ x,
                                            float* __restrict__ y){
    extern __shared__ __align__(16) char smraw[];
    u64* xs = (u64*)smraw;
    ulonglong2* tws = (ulonglong2*)(smraw + 65536);
    int tid = threadIdx.x, c = tid&63, tg = tid>>6;
    int bh = blockIdx.x, cb = blockIdx.y*128;
    const u64* in = g_A + (size_t)bh*ROWST + cb;
    const float sc = 1.0f/128.0f;   // inverse ortho total

    // Build paired spectrum Z[k] = Xc[k] + i*Xd[k], hermitian-extended.
    // pocketfft C2R ignores Im at DC/Nyquist -> zero them.
    for(int t=tid;t<65*64;t+=512){
        int k=t>>6, cc=t&63;
        ulonglong2 v = *(const ulonglong2*)&in[(size_t)k*CN + 2*cc];
        float cr,ci,dr,di; upk2(v.x,cr,ci); upk2(v.y,dr,di);
        if(k==0 || k==64){ ci = 0.0f; di = 0.0f; }
        xs[k*64+cc] = pk2(sc*(cr-di), sc*(ci+dr));
        if(k>=1 && k<=63)
            xs[(128-k)*64+cc] = pk2(sc*(cr+di), sc*(dr-ci));
    }
    if(tid<64) tws[tid] = *(const ulonglong2*)&g_twI[2*tid];
    __syncthreads();
    fft128(xs, tws, c, tg);   // inverse (e^{+i}), unnormalized

    size_t obase = (size_t)bh*(WN*CN) + cb;
    for(int s=tid;s<8192;s+=512){
        int islot=s>>6, cc=s&63;
        int w = __brev(islot)>>25;
        float yr,yi; upk2(xs[s], yr, yi);
        size_t off = obase + (size_t)w*CN + 2*cc;
        float2 bv = *(const float2*)&x[off];
        *(float2*)&y[off] = make_float2(yr+bv.x, yi+bv.y);
    }
}

// ---------------------------------------------------------------------------
extern "C" void kernel_launch(void* const* d_in, const int* in_sizes, int n_in,
                              void* d_out, int out_size) {
    const float* x  = (const float*)d_in[0];
    const float* w1 = (const float*)d_in[1];
    const float* w2 = (const float*)d_in[2];
    const float* b1 = (const float*)d_in[3];
    const float* b2 = (const float*)d_in[4];
    float* y = (float*)d_out;

    cudaFuncSetAttribute(k_s1,   cudaFuncAttributeMaxDynamicSharedMemorySize, FFT_SMEM);
    cudaFuncSetAttribute(k_ffth, cudaFuncAttributeMaxDynamicSharedMemorySize, FFT_SMEM);
    cudaFuncSetAttribute(k_s5,   cudaFuncAttributeMaxDynamicSharedMemorySize, FFT_SMEM);
    cudaFuncSetAttribute(k_mlp2, cudaFuncAttributeMaxDynamicSharedMemorySize, F_SMEM);

    k_init<<<1,128>>>();
    k_s1  <<<dim3(512,6), 512, FFT_SMEM>>>(x);
    k_ffth<<<dim3(260,12),512, FFT_SMEM>>>(0);
    k_mlp2<<<dim3(260,8), 512, F_SMEM>>>(w1, w2, b1, b2);
    k_ffth<<<dim3(260,12),512, FFT_SMEM>>>(1);
    k_s5  <<<dim3(512,6), 512, FFT_SMEM>>>(x, y);
    (void)in_sizes; (void)n_in; (void)out_size;
}